// round 3
// baseline (speedup 1.0000x reference)
#include <cuda_runtime.h>
#include <cstdint>
#include <cstddef>

#define NS     10
#define NPROJ  32
#define CCH    64
#define DD     9
#define DOUTD  4
#define PP1    2
#define PP2    4
#define PP3    4
#define PTOT   (PP1 + PP2 + PP3)
#define NT1    9
#define NT2    45
#define NT3    165
#define NT     (NT1 + NT2 + NT3)   // 219

#define CPB      4                 // channels per block (1 warp per channel)
#define NPB      256               // nodes per block (8 per thread)
#define NPAIRS   (NPB / 2)         // 128 node-pairs per channel
#define NSTREAM  4                 // f32x2 streams per thread
#define PAIR_W   18                // floats per pair row (9 ull), conflict-free
#define THREADS  128

#define SMEM_COEF_F2     (CPB * NT * DOUTD)                  // 3504 float2
#define SMEM_COEF_BYTES  (SMEM_COEF_F2 * 8)                  // 28032
#define SMEM_XS_FLOATS   (CPB * NPAIRS * PAIR_W)             // 9216
#define SMEM_BYTES       (SMEM_COEF_BYTES + SMEM_XS_FLOATS * 4)  // 64896

#define OUT_NODE_W 20              // out stage: 16 data words + 4 pad per node

typedef unsigned long long ull;

__device__ float2 g_Acoef[NS * CCH * NT * DOUTD];

__device__ __forceinline__ ull fmul2(ull a, ull b) {
    ull d; asm("mul.rn.f32x2 %0, %1, %2;" : "=l"(d) : "l"(a), "l"(b)); return d;
}
__device__ __forceinline__ ull ffma2(ull a, ull b, ull c) {
    ull d; asm("fma.rn.f32x2 %0, %1, %2, %3;" : "=l"(d) : "l"(a), "l"(b), "l"(c)); return d;
}
__device__ __forceinline__ float2 unpack2(ull v) {
    unsigned lo, hi; asm("mov.b64 {%0, %1}, %2;" : "=r"(lo), "=r"(hi) : "l"(v));
    return make_float2(__uint_as_float(lo), __uint_as_float(hi));
}

__device__ __forceinline__ int findSpecies(const int* __restrict__ counts, int n) {
    int acc = 0, s = 0;
    #pragma unroll
    for (int q = 0; q < NS; q++) {
        acc += counts[q];
        if (n >= acc) s = q + 1;
    }
    return (s < NS) ? s : (NS - 1);
}

// ---------------------------------------------------------------------------
// Prep: symmetrized coefficients  A[s][c][t][u], duplicated (v,v) for f32x2
// ---------------------------------------------------------------------------
__global__ void prep_kernel(const float* __restrict__ w,
                            const float* __restrict__ proj,
                            const float* __restrict__ u1,
                            const float* __restrict__ u2,
                            const float* __restrict__ u3) {
    int s = blockIdx.x / CCH;
    int c = blockIdx.x % CCH;
    __shared__ float wpv[PTOT];
    int tid = threadIdx.x;
    if (tid < PTOT) {
        float acc = 0.f;
        for (int a = 0; a < NPROJ; a++)
            acc += w[((size_t)s * NPROJ + a) * CCH + c] * proj[a * PTOT + tid];
        wpv[tid] = acc;
    }
    __syncthreads();

    for (int t = tid; t < NT; t += blockDim.x) {
        float cv[DOUTD];
        if (t < NT1) {
            int i = t;
            #pragma unroll
            for (int u = 0; u < DOUTD; u++) {
                float acc = 0.f;
                for (int p = 0; p < PP1; p++)
                    acc += u1[((size_t)u * DD + i) * PP1 + p] * wpv[p];
                cv[u] = acc;
            }
        } else if (t < NT1 + NT2) {
            int q = t - NT1;
            int i = 0, cnt = DD;
            while (q >= cnt) { q -= cnt; i++; cnt--; }
            int j = i + q;
            #pragma unroll
            for (int u = 0; u < DOUTD; u++) {
                float acc = 0.f;
                for (int p = 0; p < PP2; p++) {
                    float sym = u2[(((size_t)u * DD + i) * DD + j) * PP2 + p];
                    if (i != j) sym += u2[(((size_t)u * DD + j) * DD + i) * PP2 + p];
                    acc += sym * wpv[PP1 + p];
                }
                cv[u] = acc;
            }
        } else {
            int q = t - NT1 - NT2;
            int i = 0;
            for (;;) {
                int m = DD - i;
                int cnt = m * (m + 1) / 2;
                if (q < cnt) break;
                q -= cnt; i++;
            }
            int j = i;
            for (;;) {
                int cnt = DD - j;
                if (q < cnt) break;
                q -= cnt; j++;
            }
            int k = j + q;
            int pa[6], pb[6], pc[6], np = 0;
            if (i == j && j == k) {
                pa[0]=i; pb[0]=i; pc[0]=i; np = 1;
            } else if (i == j) {
                pa[0]=i; pb[0]=i; pc[0]=k;
                pa[1]=i; pb[1]=k; pc[1]=i;
                pa[2]=k; pb[2]=i; pc[2]=i; np = 3;
            } else if (j == k) {
                pa[0]=i; pb[0]=j; pc[0]=j;
                pa[1]=j; pb[1]=i; pc[1]=j;
                pa[2]=j; pb[2]=j; pc[2]=i; np = 3;
            } else {
                pa[0]=i; pb[0]=j; pc[0]=k;
                pa[1]=i; pb[1]=k; pc[1]=j;
                pa[2]=j; pb[2]=i; pc[2]=k;
                pa[3]=j; pb[3]=k; pc[3]=i;
                pa[4]=k; pb[4]=i; pc[4]=j;
                pa[5]=k; pb[5]=j; pc[5]=i; np = 6;
            }
            #pragma unroll
            for (int u = 0; u < DOUTD; u++) {
                float acc = 0.f;
                for (int m = 0; m < np; m++) {
                    const float* up = u3 + ((((size_t)u * DD + pa[m]) * DD + pb[m]) * DD + pc[m]) * PP3;
                    for (int p = 0; p < PP3; p++)
                        acc += up[p] * wpv[PP1 + PP2 + p];
                }
                cv[u] = acc;
            }
        }
        float2* dst = g_Acoef + (((size_t)(s * CCH + c)) * NT + t) * DOUTD;
        #pragma unroll
        for (int u = 0; u < DOUTD; u++) dst[u] = make_float2(cv[u], cv[u]);
    }
}

// ---------------------------------------------------------------------------
// Main: grid = (N/256, 16), 128 threads. Warp = 1 channel x 256 nodes
// (32 lanes x 4 f32x2 streams). 2 LDS.128 per monomial serve 16 FFMA2.
// ---------------------------------------------------------------------------
__global__ __launch_bounds__(THREADS, 3) void main_kernel(
    const float* __restrict__ x,
    const int* __restrict__ counts,
    float* __restrict__ out, int N)
{
    extern __shared__ char smemRaw[];
    float2* coefS = (float2*)smemRaw;
    float*  xsS   = (float*)(smemRaw + SMEM_COEF_BYTES);

    const int n0  = blockIdx.x * NPB;
    const int c0  = blockIdx.y * CPB;
    const int tid = threadIdx.x;

    int nLast = n0 + NPB - 1;
    if (nLast > N - 1) nLast = N - 1;
    const int sA = findSpecies(counts, n0);
    const int sB = findSpecies(counts, nLast);
    const bool fast = (sA == sB) && (n0 + NPB <= N);

    // Stage x into [cc][pair][2*i+parity]; pair stride 18 words -> 64-bit
    // reads at 18*pair + 2i are bank-conflict-free.
    for (int idx = tid; idx < NPB * CPB * DD; idx += THREADS) {
        int n  = idx / (CPB * DD);
        int r  = idx % (CPB * DD);
        int cc = r / DD;
        int i  = r % DD;
        int gn = n0 + n;
        float v = (gn < N) ? x[((size_t)gn * CCH + (c0 + cc)) * DD + i] : 0.f;
        xsS[(cc * NPAIRS + (n >> 1)) * PAIR_W + 2 * i + (n & 1)] = v;
    }
    if (fast) {
        const float4* src = (const float4*)(g_Acoef + ((size_t)(sA * CCH + c0)) * NT * DOUTD);
        float4* dst = (float4*)coefS;
        for (int idx = tid; idx < SMEM_COEF_F2 / 2; idx += THREADS) dst[idx] = src[idx];
    }
    __syncthreads();

    const int wslot = tid >> 5;     // channel slot 0..3
    const int lane  = tid & 31;
    const int c     = c0 + wslot;

    if (fast) {
        // Streams v=0..3: pair = lane + 32*v  (nodes 64v+2l, 64v+2l+1)
        ull xv[NSTREAM][DD];
        {
            const float* xb = xsS + (wslot * NPAIRS + lane) * PAIR_W;
            #pragma unroll
            for (int v = 0; v < NSTREAM; v++)
                #pragma unroll
                for (int i = 0; i < DD; i++)
                    xv[v][i] = *(const ull*)(xb + v * 32 * PAIR_W + 2 * i);
        }

        const float2* cf = coefS + (size_t)wslot * NT * DOUTD;
        ull acc[NSTREAM][DOUTD];
        #pragma unroll
        for (int v = 0; v < NSTREAM; v++)
            #pragma unroll
            for (int u = 0; u < DOUTD; u++) acc[v][u] = 0;

        int t2 = NT1, t3 = NT1 + NT2;
        #pragma unroll
        for (int i = 0; i < DD; i++) {
            {
                const ulonglong2* cp = (const ulonglong2*)(cf + i * DOUTD);
                ulonglong2 lo = cp[0], hi = cp[1];
                #pragma unroll
                for (int v = 0; v < NSTREAM; v++) {
                    acc[v][0] = ffma2(xv[v][i], lo.x, acc[v][0]);
                    acc[v][1] = ffma2(xv[v][i], lo.y, acc[v][1]);
                    acc[v][2] = ffma2(xv[v][i], hi.x, acc[v][2]);
                    acc[v][3] = ffma2(xv[v][i], hi.y, acc[v][3]);
                }
            }
            #pragma unroll
            for (int j = i; j < DD; j++) {
                ull pij[NSTREAM];
                #pragma unroll
                for (int v = 0; v < NSTREAM; v++) pij[v] = fmul2(xv[v][i], xv[v][j]);
                {
                    const ulonglong2* cp = (const ulonglong2*)(cf + t2 * DOUTD);
                    ulonglong2 lo = cp[0], hi = cp[1];
                    #pragma unroll
                    for (int v = 0; v < NSTREAM; v++) {
                        acc[v][0] = ffma2(pij[v], lo.x, acc[v][0]);
                        acc[v][1] = ffma2(pij[v], lo.y, acc[v][1]);
                        acc[v][2] = ffma2(pij[v], hi.x, acc[v][2]);
                        acc[v][3] = ffma2(pij[v], hi.y, acc[v][3]);
                    }
                }
                t2++;
                #pragma unroll
                for (int k = j; k < DD; k++) {
                    const ulonglong2* cp = (const ulonglong2*)(cf + t3 * DOUTD);
                    ulonglong2 lo = cp[0], hi = cp[1];
                    #pragma unroll
                    for (int v = 0; v < NSTREAM; v++) {
                        ull m = fmul2(pij[v], xv[v][k]);
                        acc[v][0] = ffma2(m, lo.x, acc[v][0]);
                        acc[v][1] = ffma2(m, lo.y, acc[v][1]);
                        acc[v][2] = ffma2(m, hi.x, acc[v][2]);
                        acc[v][3] = ffma2(m, hi.y, acc[v][3]);
                    }
                    t3++;
                }
            }
        }

        // Stage results into smem (coef region dead), then coalesced store.
        __syncthreads();
        float* outS = (float*)coefS;   // [node][OUT_NODE_W]
        #pragma unroll
        for (int v = 0; v < NSTREAM; v++) {
            float2 r0 = unpack2(acc[v][0]), r1 = unpack2(acc[v][1]);
            float2 r2 = unpack2(acc[v][2]), r3 = unpack2(acc[v][3]);
            int nodeBase = 64 * v + 2 * lane;
            *(float4*)(outS + (nodeBase + 0) * OUT_NODE_W + wslot * 4) =
                make_float4(r0.x, r1.x, r2.x, r3.x);
            *(float4*)(outS + (nodeBase + 1) * OUT_NODE_W + wslot * 4) =
                make_float4(r0.y, r1.y, r2.y, r3.y);
        }
        __syncthreads();
        float4* out4 = (float4*)out;
        #pragma unroll
        for (int g = tid; g < NPB * CPB; g += THREADS) {
            int node = g >> 2;
            int q    = g & 3;
            float4 vv = *(const float4*)(outS + node * OUT_NODE_W + q * 4);
            out4[(size_t)(n0 + node) * CCH + c0 + q] = vv;
        }
    } else {
        // Cold path: boundary / mixed-species / partial blocks.
        #pragma unroll 1
        for (int h = 0; h < 2 * NSTREAM; h++) {
            int pair   = lane + 32 * (h >> 1);
            int parity = h & 1;
            int n = n0 + 2 * pair + parity;
            if (n >= N) continue;
            int s = findSpecies(counts, n);
            const float2* cfg = g_Acoef + ((size_t)(s * CCH + c)) * NT * DOUTD;
            float xs[DD];
            const float* xb = xsS + (wslot * NPAIRS + pair) * PAIR_W;
            #pragma unroll
            for (int i = 0; i < DD; i++) xs[i] = xb[2 * i + parity];
            float a[DOUTD] = {0.f, 0.f, 0.f, 0.f};
            int t2 = NT1, t3 = NT1 + NT2;
            #pragma unroll 1
            for (int i = 0; i < DD; i++) {
                #pragma unroll
                for (int u = 0; u < DOUTD; u++) a[u] += cfg[i * DOUTD + u].x * xs[i];
                #pragma unroll 1
                for (int j = i; j < DD; j++) {
                    float pij = xs[i] * xs[j];
                    #pragma unroll
                    for (int u = 0; u < DOUTD; u++) a[u] += cfg[t2 * DOUTD + u].x * pij;
                    t2++;
                    #pragma unroll 1
                    for (int k = j; k < DD; k++) {
                        float m = pij * xs[k];
                        #pragma unroll
                        for (int u = 0; u < DOUTD; u++) a[u] += cfg[t3 * DOUTD + u].x * m;
                        t3++;
                    }
                }
            }
            float4* outp = (float4*)out;
            outp[(size_t)n * CCH + c] = make_float4(a[0], a[1], a[2], a[3]);
        }
    }
}

extern "C" void kernel_launch(void* const* d_in, const int* in_sizes, int n_in,
                              void* d_out, int out_size) {
    const float* x     = (const float*)d_in[0];
    const float* w     = (const float*)d_in[1];
    const float* proj  = (const float*)d_in[2];
    const float* u1    = (const float*)d_in[3];
    const float* u2    = (const float*)d_in[4];
    const float* u3    = (const float*)d_in[5];
    const int*   cnts  = (const int*)d_in[6];
    float* out = (float*)d_out;

    int N = in_sizes[0] / (CCH * DD);

    cudaFuncSetAttribute(main_kernel, cudaFuncAttributeMaxDynamicSharedMemorySize, SMEM_BYTES);

    prep_kernel<<<NS * CCH, 256>>>(w, proj, u1, u2, u3);

    dim3 grid((N + NPB - 1) / NPB, CCH / CPB);
    main_kernel<<<grid, THREADS, SMEM_BYTES>>>(x, cnts, out, N);
}

// round 5
// speedup vs baseline: 2.1998x; 2.1998x over previous
#include <cuda_runtime.h>
#include <cstdint>
#include <cstddef>

#define NS     10
#define NPROJ  32
#define CCH    64
#define DD     9
#define DOUTD  4
#define PP1    2
#define PP2    4
#define PP3    4
#define PTOT   (PP1 + PP2 + PP3)
#define NT1    9
#define NT2    45
#define NT3    165
#define NT     (NT1 + NT2 + NT3)   // 219

#define CPB      4                 // channels per block (1 warp per channel)
#define NSTREAM  3                 // f32x2 streams per thread (register-budgeted)
#define NPB      (NSTREAM * 64)    // 192 nodes per block
#define NPAIRS   (NPB / 2)         // 96 node-pairs per channel
#define PAIR_W   18                // floats per pair row (9 ull), conflict-free
#define THREADS  128

#define SMEM_COEF_F2     (CPB * NT * DOUTD)                  // 3504 float2
#define SMEM_COEF_BYTES  (SMEM_COEF_F2 * 8)                  // 28032
#define SMEM_XS_FLOATS   (CPB * NPAIRS * PAIR_W)             // 6912
#define SMEM_BYTES       (SMEM_COEF_BYTES + SMEM_XS_FLOATS * 4)  // 55680

#define OUT_NODE_W 20              // out stage: 16 data words + 4 pad per node

typedef unsigned long long ull;

__device__ float2 g_Acoef[NS * CCH * NT * DOUTD];

__device__ __forceinline__ ull fmul2(ull a, ull b) {
    ull d; asm("mul.rn.f32x2 %0, %1, %2;" : "=l"(d) : "l"(a), "l"(b)); return d;
}
__device__ __forceinline__ ull ffma2(ull a, ull b, ull c) {
    ull d; asm("fma.rn.f32x2 %0, %1, %2, %3;" : "=l"(d) : "l"(a), "l"(b), "l"(c)); return d;
}
__device__ __forceinline__ float2 unpack2(ull v) {
    unsigned lo, hi; asm("mov.b64 {%0, %1}, %2;" : "=r"(lo), "=r"(hi) : "l"(v));
    return make_float2(__uint_as_float(lo), __uint_as_float(hi));
}

// ---------------------------------------------------------------------------
// Prep: symmetrized coefficients  A[s][c][t][u], duplicated (v,v) for f32x2
// ---------------------------------------------------------------------------
__global__ void prep_kernel(const float* __restrict__ w,
                            const float* __restrict__ proj,
                            const float* __restrict__ u1,
                            const float* __restrict__ u2,
                            const float* __restrict__ u3) {
    int s = blockIdx.x / CCH;
    int c = blockIdx.x % CCH;
    __shared__ float wpv[PTOT];
    int tid = threadIdx.x;
    if (tid < PTOT) {
        float acc = 0.f;
        for (int a = 0; a < NPROJ; a++)
            acc += w[((size_t)s * NPROJ + a) * CCH + c] * proj[a * PTOT + tid];
        wpv[tid] = acc;
    }
    __syncthreads();

    for (int t = tid; t < NT; t += blockDim.x) {
        float cv[DOUTD];
        if (t < NT1) {
            int i = t;
            #pragma unroll
            for (int u = 0; u < DOUTD; u++) {
                float acc = 0.f;
                for (int p = 0; p < PP1; p++)
                    acc += u1[((size_t)u * DD + i) * PP1 + p] * wpv[p];
                cv[u] = acc;
            }
        } else if (t < NT1 + NT2) {
            int q = t - NT1;
            int i = 0, cnt = DD;
            while (q >= cnt) { q -= cnt; i++; cnt--; }
            int j = i + q;
            #pragma unroll
            for (int u = 0; u < DOUTD; u++) {
                float acc = 0.f;
                for (int p = 0; p < PP2; p++) {
                    float sym = u2[(((size_t)u * DD + i) * DD + j) * PP2 + p];
                    if (i != j) sym += u2[(((size_t)u * DD + j) * DD + i) * PP2 + p];
                    acc += sym * wpv[PP1 + p];
                }
                cv[u] = acc;
            }
        } else {
            int q = t - NT1 - NT2;
            int i = 0;
            for (;;) {
                int m = DD - i;
                int cnt = m * (m + 1) / 2;
                if (q < cnt) break;
                q -= cnt; i++;
            }
            int j = i;
            for (;;) {
                int cnt = DD - j;
                if (q < cnt) break;
                q -= cnt; j++;
            }
            int k = j + q;
            int pa[6], pb[6], pc[6], np = 0;
            if (i == j && j == k) {
                pa[0]=i; pb[0]=i; pc[0]=i; np = 1;
            } else if (i == j) {
                pa[0]=i; pb[0]=i; pc[0]=k;
                pa[1]=i; pb[1]=k; pc[1]=i;
                pa[2]=k; pb[2]=i; pc[2]=i; np = 3;
            } else if (j == k) {
                pa[0]=i; pb[0]=j; pc[0]=j;
                pa[1]=j; pb[1]=i; pc[1]=j;
                pa[2]=j; pb[2]=j; pc[2]=i; np = 3;
            } else {
                pa[0]=i; pb[0]=j; pc[0]=k;
                pa[1]=i; pb[1]=k; pc[1]=j;
                pa[2]=j; pb[2]=i; pc[2]=k;
                pa[3]=j; pb[3]=k; pc[3]=i;
                pa[4]=k; pb[4]=i; pc[4]=j;
                pa[5]=k; pb[5]=j; pc[5]=i; np = 6;
            }
            #pragma unroll
            for (int u = 0; u < DOUTD; u++) {
                float acc = 0.f;
                for (int m = 0; m < np; m++) {
                    const float* up = u3 + ((((size_t)u * DD + pa[m]) * DD + pb[m]) * DD + pc[m]) * PP3;
                    for (int p = 0; p < PP3; p++)
                        acc += up[p] * wpv[PP1 + PP2 + p];
                }
                cv[u] = acc;
            }
        }
        float2* dst = g_Acoef + (((size_t)(s * CCH + c)) * NT + t) * DOUTD;
        #pragma unroll
        for (int u = 0; u < DOUTD; u++) dst[u] = make_float2(cv[u], cv[u]);
    }
}

// ---------------------------------------------------------------------------
// Fast evaluator: NSTR f32x2 streams; coefficients smem-broadcast.
// Results returned in registers (acc) — NO smem writes here, so the caller
// can safely reuse the coefficient region after a __syncthreads().
// ---------------------------------------------------------------------------
template <int NSTR>
__device__ __forceinline__ void eval_streams(
    const float* __restrict__ xsS, const float2* __restrict__ cf,
    ull (&acc)[NSTREAM][DOUTD], int wslot, int lane)
{
    ull xv[NSTR][DD];
    {
        const float* xb = xsS + (wslot * NPAIRS + lane) * PAIR_W;
        #pragma unroll
        for (int v = 0; v < NSTR; v++)
            #pragma unroll
            for (int i = 0; i < DD; i++)
                xv[v][i] = *(const ull*)(xb + v * 32 * PAIR_W + 2 * i);
    }

    #pragma unroll
    for (int v = 0; v < NSTR; v++)
        #pragma unroll
        for (int u = 0; u < DOUTD; u++) acc[v][u] = 0;

    int t2 = NT1, t3 = NT1 + NT2;
    #pragma unroll
    for (int i = 0; i < DD; i++) {
        {
            const ulonglong2* cp = (const ulonglong2*)(cf + i * DOUTD);
            ulonglong2 lo = cp[0], hi = cp[1];
            #pragma unroll
            for (int v = 0; v < NSTR; v++) {
                acc[v][0] = ffma2(xv[v][i], lo.x, acc[v][0]);
                acc[v][1] = ffma2(xv[v][i], lo.y, acc[v][1]);
                acc[v][2] = ffma2(xv[v][i], hi.x, acc[v][2]);
                acc[v][3] = ffma2(xv[v][i], hi.y, acc[v][3]);
            }
        }
        #pragma unroll
        for (int j = i; j < DD; j++) {
            ull pij[NSTR];
            #pragma unroll
            for (int v = 0; v < NSTR; v++) pij[v] = fmul2(xv[v][i], xv[v][j]);
            {
                const ulonglong2* cp = (const ulonglong2*)(cf + t2 * DOUTD);
                ulonglong2 lo = cp[0], hi = cp[1];
                #pragma unroll
                for (int v = 0; v < NSTR; v++) {
                    acc[v][0] = ffma2(pij[v], lo.x, acc[v][0]);
                    acc[v][1] = ffma2(pij[v], lo.y, acc[v][1]);
                    acc[v][2] = ffma2(pij[v], hi.x, acc[v][2]);
                    acc[v][3] = ffma2(pij[v], hi.y, acc[v][3]);
                }
            }
            t2++;
            #pragma unroll
            for (int k = j; k < DD; k++) {
                const ulonglong2* cp = (const ulonglong2*)(cf + t3 * DOUTD);
                ulonglong2 lo = cp[0], hi = cp[1];
                #pragma unroll
                for (int v = 0; v < NSTR; v++) {
                    ull m = fmul2(pij[v], xv[v][k]);
                    acc[v][0] = ffma2(m, lo.x, acc[v][0]);
                    acc[v][1] = ffma2(m, lo.y, acc[v][1]);
                    acc[v][2] = ffma2(m, hi.x, acc[v][2]);
                    acc[v][3] = ffma2(m, hi.y, acc[v][3]);
                }
                t3++;
            }
        }
    }
}

// ---------------------------------------------------------------------------
// Main: per-species block assignment. grid = (ceil(N/192)+NS, 16), 128 thr.
// Every block is single-species; 128-node species tails use eval_streams<2>.
// ---------------------------------------------------------------------------
__global__ __launch_bounds__(THREADS, 3) void main_kernel(
    const float* __restrict__ x,
    const int* __restrict__ counts,
    float* __restrict__ out, int N)
{
    extern __shared__ char smemRaw[];
    float2* coefS = (float2*)smemRaw;
    float*  xsS   = (float*)(smemRaw + SMEM_COEF_BYTES);

    // ---- per-species block assignment (block-uniform walk over counts) ----
    int b = blockIdx.x;
    int sMy = -1, n0 = 0, avail = 0;
    {
        int base = 0;
        #pragma unroll 1
        for (int s = 0; s < NS; s++) {
            int cnt = counts[s];
            int nb  = (cnt + NPB - 1) / NPB;
            if (b < nb) {
                sMy   = s;
                n0    = base + b * NPB;
                avail = cnt - b * NPB;
                if (avail > NPB) avail = NPB;
                break;
            }
            b    -= nb;
            base += cnt;
        }
    }
    if (sMy < 0) return;

    const int c0  = blockIdx.y * CPB;
    const int tid = threadIdx.x;

    // Stage x into [cc][pair][2*i+parity]; pair stride 18 words -> conflict-free
    for (int idx = tid; idx < NPB * CPB * DD; idx += THREADS) {
        int n  = idx / (CPB * DD);
        int r  = idx % (CPB * DD);
        int cc = r / DD;
        int i  = r % DD;
        float v = (n < avail) ? x[((size_t)(n0 + n) * CCH + (c0 + cc)) * DD + i] : 0.f;
        xsS[(cc * NPAIRS + (n >> 1)) * PAIR_W + 2 * i + (n & 1)] = v;
    }
    // Stage coefficients for this (species, channel group)
    {
        const float4* src = (const float4*)(g_Acoef + ((size_t)(sMy * CCH + c0)) * NT * DOUTD);
        float4* dst = (float4*)coefS;
        for (int idx = tid; idx < SMEM_COEF_F2 / 2; idx += THREADS) dst[idx] = src[idx];
    }
    __syncthreads();

    const int wslot = tid >> 5;
    const int lane  = tid & 31;
    const int vmax  = avail >> 6;          // full 64-node streams (block-uniform)

    const float2* cf = coefS + (size_t)wslot * NT * DOUTD;

    if (vmax > 0) {
        ull acc[NSTREAM][DOUTD];
        if (vmax >= 3)      eval_streams<3>(xsS, cf, acc, wslot, lane);
        else if (vmax == 2) eval_streams<2>(xsS, cf, acc, wslot, lane);
        else                eval_streams<1>(xsS, cf, acc, wslot, lane);

        // All coefficient reads complete -> safe to reuse the region for output
        __syncthreads();
        float* outS = (float*)coefS;       // [node][OUT_NODE_W]
        #pragma unroll
        for (int v = 0; v < NSTREAM; v++) {
            if (v >= vmax) break;
            float2 r0 = unpack2(acc[v][0]), r1 = unpack2(acc[v][1]);
            float2 r2 = unpack2(acc[v][2]), r3 = unpack2(acc[v][3]);
            int nodeBase = 64 * v + 2 * lane;
            *(float4*)(outS + (nodeBase + 0) * OUT_NODE_W + wslot * 4) =
                make_float4(r0.x, r1.x, r2.x, r3.x);
            *(float4*)(outS + (nodeBase + 1) * OUT_NODE_W + wslot * 4) =
                make_float4(r0.y, r1.y, r2.y, r3.y);
        }
        __syncthreads();
        // Coalesced cooperative store of vmax*64 nodes
        float4* out4 = (float4*)out;
        int total = (vmax << 6) * CPB;
        for (int g = tid; g < total; g += THREADS) {
            int node = g >> 2;
            int q    = g & 3;
            float4 vv = *(const float4*)(outS + node * OUT_NODE_W + q * 4);
            out4[(size_t)(n0 + node) * CCH + c0 + q] = vv;
        }
    }

    // Remainder nodes (avail % 64): scalar path, coefs from global.
    // (Never taken with uniform 3200-per-species counts; kept for generality.)
    int remStart = vmax << 6;
    if (remStart < avail) {
        const int c = c0 + wslot;
        const float2* cfg = g_Acoef + ((size_t)(sMy * CCH + c)) * NT * DOUTD;
        #pragma unroll 1
        for (int k = remStart + lane; k < avail; k += 32) {
            float xs[DD];
            const float* xb = xsS + (wslot * NPAIRS + (k >> 1)) * PAIR_W;
            #pragma unroll
            for (int i = 0; i < DD; i++) xs[i] = xb[2 * i + (k & 1)];
            float a[DOUTD] = {0.f, 0.f, 0.f, 0.f};
            int t2 = NT1, t3 = NT1 + NT2;
            #pragma unroll 1
            for (int i = 0; i < DD; i++) {
                #pragma unroll
                for (int u = 0; u < DOUTD; u++) a[u] += cfg[i * DOUTD + u].x * xs[i];
                #pragma unroll 1
                for (int j = i; j < DD; j++) {
                    float pij = xs[i] * xs[j];
                    #pragma unroll
                    for (int u = 0; u < DOUTD; u++) a[u] += cfg[t2 * DOUTD + u].x * pij;
                    t2++;
                    #pragma unroll 1
                    for (int kk = j; kk < DD; kk++) {
                        float m = pij * xs[kk];
                        #pragma unroll
                        for (int u = 0; u < DOUTD; u++) a[u] += cfg[t3 * DOUTD + u].x * m;
                        t3++;
                    }
                }
            }
            float4* outp = (float4*)out;
            outp[(size_t)(n0 + k) * CCH + c] = make_float4(a[0], a[1], a[2], a[3]);
        }
    }
}

extern "C" void kernel_launch(void* const* d_in, const int* in_sizes, int n_in,
                              void* d_out, int out_size) {
    const float* x     = (const float*)d_in[0];
    const float* w     = (const float*)d_in[1];
    const float* proj  = (const float*)d_in[2];
    const float* u1    = (const float*)d_in[3];
    const float* u2    = (const float*)d_in[4];
    const float* u3    = (const float*)d_in[5];
    const int*   cnts  = (const int*)d_in[6];
    float* out = (float*)d_out;

    int N = in_sizes[0] / (CCH * DD);

    cudaFuncSetAttribute(main_kernel, cudaFuncAttributeMaxDynamicSharedMemorySize, SMEM_BYTES);

    prep_kernel<<<NS * CCH, 256>>>(w, proj, u1, u2, u3);

    dim3 grid((N + NPB - 1) / NPB + NS, CCH / CPB);
    main_kernel<<<grid, THREADS, SMEM_BYTES>>>(x, cnts, out, N);
}

// round 6
// speedup vs baseline: 3.0639x; 1.3928x over previous
#include <cuda_runtime.h>
#include <cstdint>
#include <cstddef>

#define NS     10
#define NPROJ  32
#define CCH    64
#define DD     9
#define DOUTD  4
#define PP1    2
#define PP2    4
#define PP3    4
#define PTOT   (PP1 + PP2 + PP3)
#define NT1    9
#define NT2    45
#define NT3    165
#define NT     (NT1 + NT2 + NT3)   // 219

#define CPB      4                 // channels per block (1 warp per channel)
#define NSTREAM  2                 // f32x2 streams per thread (occupancy-budgeted)
#define NPB      (NSTREAM * 64)    // 128 nodes per block
#define NPAIRS   (NPB / 2)         // 64 node-pairs per channel
#define PAIR_W   18                // words per pair row (9 ull), conflict-free reads
#define XS_CC_W  (NPAIRS * PAIR_W + 8)  // 1160: +8 pad kills staging-store conflicts
#define THREADS  128

#define SMEM_COEF_F2     (CPB * NT * DOUTD)                  // 3504 float2
#define SMEM_COEF_BYTES  (SMEM_COEF_F2 * 8)                  // 28032
#define SMEM_XS_FLOATS   (CPB * XS_CC_W)                     // 4640
#define SMEM_BYTES       (SMEM_COEF_BYTES + SMEM_XS_FLOATS * 4)  // 46592

#define OUT_NODE_W 20              // out stage: 16 data words + 4 pad per node

typedef unsigned long long ull;

__device__ float2 g_Acoef[NS * CCH * NT * DOUTD];

__device__ __forceinline__ ull fmul2(ull a, ull b) {
    ull d; asm("mul.rn.f32x2 %0, %1, %2;" : "=l"(d) : "l"(a), "l"(b)); return d;
}
__device__ __forceinline__ ull ffma2(ull a, ull b, ull c) {
    ull d; asm("fma.rn.f32x2 %0, %1, %2, %3;" : "=l"(d) : "l"(a), "l"(b), "l"(c)); return d;
}
__device__ __forceinline__ float2 unpack2(ull v) {
    unsigned lo, hi; asm("mov.b64 {%0, %1}, %2;" : "=r"(lo), "=r"(hi) : "l"(v));
    return make_float2(__uint_as_float(lo), __uint_as_float(hi));
}

// ---------------------------------------------------------------------------
// Prep: symmetrized coefficients  A[s][c][t][u], duplicated (v,v) for f32x2
// ---------------------------------------------------------------------------
__global__ void prep_kernel(const float* __restrict__ w,
                            const float* __restrict__ proj,
                            const float* __restrict__ u1,
                            const float* __restrict__ u2,
                            const float* __restrict__ u3) {
    int s = blockIdx.x / CCH;
    int c = blockIdx.x % CCH;
    __shared__ float wpv[PTOT];
    int tid = threadIdx.x;
    if (tid < PTOT) {
        float acc = 0.f;
        for (int a = 0; a < NPROJ; a++)
            acc += w[((size_t)s * NPROJ + a) * CCH + c] * proj[a * PTOT + tid];
        wpv[tid] = acc;
    }
    __syncthreads();

    for (int t = tid; t < NT; t += blockDim.x) {
        float cv[DOUTD];
        if (t < NT1) {
            int i = t;
            #pragma unroll
            for (int u = 0; u < DOUTD; u++) {
                float acc = 0.f;
                for (int p = 0; p < PP1; p++)
                    acc += u1[((size_t)u * DD + i) * PP1 + p] * wpv[p];
                cv[u] = acc;
            }
        } else if (t < NT1 + NT2) {
            int q = t - NT1;
            int i = 0, cnt = DD;
            while (q >= cnt) { q -= cnt; i++; cnt--; }
            int j = i + q;
            #pragma unroll
            for (int u = 0; u < DOUTD; u++) {
                float acc = 0.f;
                for (int p = 0; p < PP2; p++) {
                    float sym = u2[(((size_t)u * DD + i) * DD + j) * PP2 + p];
                    if (i != j) sym += u2[(((size_t)u * DD + j) * DD + i) * PP2 + p];
                    acc += sym * wpv[PP1 + p];
                }
                cv[u] = acc;
            }
        } else {
            int q = t - NT1 - NT2;
            int i = 0;
            for (;;) {
                int m = DD - i;
                int cnt = m * (m + 1) / 2;
                if (q < cnt) break;
                q -= cnt; i++;
            }
            int j = i;
            for (;;) {
                int cnt = DD - j;
                if (q < cnt) break;
                q -= cnt; j++;
            }
            int k = j + q;
            int pa[6], pb[6], pc[6], np = 0;
            if (i == j && j == k) {
                pa[0]=i; pb[0]=i; pc[0]=i; np = 1;
            } else if (i == j) {
                pa[0]=i; pb[0]=i; pc[0]=k;
                pa[1]=i; pb[1]=k; pc[1]=i;
                pa[2]=k; pb[2]=i; pc[2]=i; np = 3;
            } else if (j == k) {
                pa[0]=i; pb[0]=j; pc[0]=j;
                pa[1]=j; pb[1]=i; pc[1]=j;
                pa[2]=j; pb[2]=j; pc[2]=i; np = 3;
            } else {
                pa[0]=i; pb[0]=j; pc[0]=k;
                pa[1]=i; pb[1]=k; pc[1]=j;
                pa[2]=j; pb[2]=i; pc[2]=k;
                pa[3]=j; pb[3]=k; pc[3]=i;
                pa[4]=k; pb[4]=i; pc[4]=j;
                pa[5]=k; pb[5]=j; pc[5]=i; np = 6;
            }
            #pragma unroll
            for (int u = 0; u < DOUTD; u++) {
                float acc = 0.f;
                for (int m = 0; m < np; m++) {
                    const float* up = u3 + ((((size_t)u * DD + pa[m]) * DD + pb[m]) * DD + pc[m]) * PP3;
                    for (int p = 0; p < PP3; p++)
                        acc += up[p] * wpv[PP1 + PP2 + p];
                }
                cv[u] = acc;
            }
        }
        float2* dst = g_Acoef + (((size_t)(s * CCH + c)) * NT + t) * DOUTD;
        #pragma unroll
        for (int u = 0; u < DOUTD; u++) dst[u] = make_float2(cv[u], cv[u]);
    }
}

// ---------------------------------------------------------------------------
// Fast evaluator: NSTR f32x2 streams; coefficients smem-broadcast.
// Results returned in registers — NO smem writes here (coef region stays live).
// ---------------------------------------------------------------------------
template <int NSTR>
__device__ __forceinline__ void eval_streams(
    const float* __restrict__ xsS, const float2* __restrict__ cf,
    ull (&acc)[NSTREAM][DOUTD], int wslot, int lane)
{
    ull xv[NSTR][DD];
    {
        const float* xb = xsS + wslot * XS_CC_W + lane * PAIR_W;
        #pragma unroll
        for (int v = 0; v < NSTR; v++)
            #pragma unroll
            for (int i = 0; i < DD; i++)
                xv[v][i] = *(const ull*)(xb + v * 32 * PAIR_W + 2 * i);
    }

    #pragma unroll
    for (int v = 0; v < NSTR; v++)
        #pragma unroll
        for (int u = 0; u < DOUTD; u++) acc[v][u] = 0;

    int t2 = NT1, t3 = NT1 + NT2;
    #pragma unroll
    for (int i = 0; i < DD; i++) {
        {
            const ulonglong2* cp = (const ulonglong2*)(cf + i * DOUTD);
            ulonglong2 lo = cp[0], hi = cp[1];
            #pragma unroll
            for (int v = 0; v < NSTR; v++) {
                acc[v][0] = ffma2(xv[v][i], lo.x, acc[v][0]);
                acc[v][1] = ffma2(xv[v][i], lo.y, acc[v][1]);
                acc[v][2] = ffma2(xv[v][i], hi.x, acc[v][2]);
                acc[v][3] = ffma2(xv[v][i], hi.y, acc[v][3]);
            }
        }
        #pragma unroll
        for (int j = i; j < DD; j++) {
            ull pij[NSTR];
            #pragma unroll
            for (int v = 0; v < NSTR; v++) pij[v] = fmul2(xv[v][i], xv[v][j]);
            {
                const ulonglong2* cp = (const ulonglong2*)(cf + t2 * DOUTD);
                ulonglong2 lo = cp[0], hi = cp[1];
                #pragma unroll
                for (int v = 0; v < NSTR; v++) {
                    acc[v][0] = ffma2(pij[v], lo.x, acc[v][0]);
                    acc[v][1] = ffma2(pij[v], lo.y, acc[v][1]);
                    acc[v][2] = ffma2(pij[v], hi.x, acc[v][2]);
                    acc[v][3] = ffma2(pij[v], hi.y, acc[v][3]);
                }
            }
            t2++;
            #pragma unroll
            for (int k = j; k < DD; k++) {
                const ulonglong2* cp = (const ulonglong2*)(cf + t3 * DOUTD);
                ulonglong2 lo = cp[0], hi = cp[1];
                #pragma unroll
                for (int v = 0; v < NSTR; v++) {
                    ull m = fmul2(pij[v], xv[v][k]);
                    acc[v][0] = ffma2(m, lo.x, acc[v][0]);
                    acc[v][1] = ffma2(m, lo.y, acc[v][1]);
                    acc[v][2] = ffma2(m, hi.x, acc[v][2]);
                    acc[v][3] = ffma2(m, hi.y, acc[v][3]);
                }
                t3++;
            }
        }
    }
}

// ---------------------------------------------------------------------------
// Main: per-species block assignment. grid = (ceil(N/128)+NS, 16), 128 thr,
// 5 blocks/SM target (regs<=102, smem 46592).
// ---------------------------------------------------------------------------
__global__ __launch_bounds__(THREADS, 5) void main_kernel(
    const float* __restrict__ x,
    const int* __restrict__ counts,
    float* __restrict__ out, int N)
{
    extern __shared__ char smemRaw[];
    float2* coefS = (float2*)smemRaw;
    float*  xsS   = (float*)(smemRaw + SMEM_COEF_BYTES);

    // ---- per-species block assignment (block-uniform walk over counts) ----
    int b = blockIdx.x;
    int sMy = -1, n0 = 0, avail = 0;
    {
        int base = 0;
        #pragma unroll 1
        for (int s = 0; s < NS; s++) {
            int cnt = counts[s];
            int nb  = (cnt + NPB - 1) / NPB;
            if (b < nb) {
                sMy   = s;
                n0    = base + b * NPB;
                avail = cnt - b * NPB;
                if (avail > NPB) avail = NPB;
                break;
            }
            b    -= nb;
            base += cnt;
        }
    }
    if (sMy < 0) return;

    const int c0  = blockIdx.y * CPB;
    const int tid = threadIdx.x;

    // Stage x: div-free. tid -> (n%32, cc); loop covers 4 node groups x 9 i.
    {
        const int nnB = tid >> 2;        // node within group (0..31)
        const int cc  = tid & 3;
        #pragma unroll
        for (int rep = 0; rep < NPB / 32; rep++) {
            int n = nnB + rep * 32;
            const float* xg = x + ((size_t)(n0 + n) * CCH + (c0 + cc)) * DD;
            float* xd = xsS + cc * XS_CC_W + (n >> 1) * PAIR_W + (n & 1);
            bool ok = (n < avail);
            #pragma unroll
            for (int i = 0; i < DD; i++)
                xd[2 * i] = ok ? xg[i] : 0.f;
        }
    }
    // Stage coefficients for this (species, channel group)
    {
        const float4* src = (const float4*)(g_Acoef + ((size_t)(sMy * CCH + c0)) * NT * DOUTD);
        float4* dst = (float4*)coefS;
        for (int idx = tid; idx < SMEM_COEF_F2 / 2; idx += THREADS) dst[idx] = src[idx];
    }
    __syncthreads();

    const int wslot = tid >> 5;
    const int lane  = tid & 31;
    const int vmax  = avail >> 6;          // full 64-node streams (block-uniform)

    const float2* cf = coefS + (size_t)wslot * NT * DOUTD;

    if (vmax > 0) {
        ull acc[NSTREAM][DOUTD];
        if (vmax >= 2) eval_streams<2>(xsS, cf, acc, wslot, lane);
        else           eval_streams<1>(xsS, cf, acc, wslot, lane);

        // All coefficient reads complete -> safe to reuse region for output
        __syncthreads();
        float* outS = (float*)coefS;       // [node][OUT_NODE_W]
        #pragma unroll
        for (int v = 0; v < NSTREAM; v++) {
            if (v >= vmax) break;
            float2 r0 = unpack2(acc[v][0]), r1 = unpack2(acc[v][1]);
            float2 r2 = unpack2(acc[v][2]), r3 = unpack2(acc[v][3]);
            int nodeBase = 64 * v + 2 * lane;
            *(float4*)(outS + (nodeBase + 0) * OUT_NODE_W + wslot * 4) =
                make_float4(r0.x, r1.x, r2.x, r3.x);
            *(float4*)(outS + (nodeBase + 1) * OUT_NODE_W + wslot * 4) =
                make_float4(r0.y, r1.y, r2.y, r3.y);
        }
        __syncthreads();
        // Coalesced cooperative store of vmax*64 nodes
        float4* out4 = (float4*)out;
        int total = (vmax << 6) * CPB;
        for (int g = tid; g < total; g += THREADS) {
            int node = g >> 2;
            int q    = g & 3;
            float4 vv = *(const float4*)(outS + node * OUT_NODE_W + q * 4);
            out4[(size_t)(n0 + node) * CCH + c0 + q] = vv;
        }
    }

    // Remainder nodes (avail % 64): scalar path (never taken for uniform counts)
    int remStart = vmax << 6;
    if (remStart < avail) {
        const int c = c0 + wslot;
        const float2* cfg = g_Acoef + ((size_t)(sMy * CCH + c)) * NT * DOUTD;
        #pragma unroll 1
        for (int k = remStart + lane; k < avail; k += 32) {
            float xs[DD];
            const float* xb = xsS + wslot * XS_CC_W + (k >> 1) * PAIR_W;
            #pragma unroll
            for (int i = 0; i < DD; i++) xs[i] = xb[2 * i + (k & 1)];
            float a[DOUTD] = {0.f, 0.f, 0.f, 0.f};
            int t2 = NT1, t3 = NT1 + NT2;
            #pragma unroll 1
            for (int i = 0; i < DD; i++) {
                #pragma unroll
                for (int u = 0; u < DOUTD; u++) a[u] += cfg[i * DOUTD + u].x * xs[i];
                #pragma unroll 1
                for (int j = i; j < DD; j++) {
                    float pij = xs[i] * xs[j];
                    #pragma unroll
                    for (int u = 0; u < DOUTD; u++) a[u] += cfg[t2 * DOUTD + u].x * pij;
                    t2++;
                    #pragma unroll 1
                    for (int kk = j; kk < DD; kk++) {
                        float m = pij * xs[kk];
                        #pragma unroll
                        for (int u = 0; u < DOUTD; u++) a[u] += cfg[t3 * DOUTD + u].x * m;
                        t3++;
                    }
                }
            }
            float4* outp = (float4*)out;
            outp[(size_t)(n0 + k) * CCH + c] = make_float4(a[0], a[1], a[2], a[3]);
        }
    }
}

extern "C" void kernel_launch(void* const* d_in, const int* in_sizes, int n_in,
                              void* d_out, int out_size) {
    const float* x     = (const float*)d_in[0];
    const float* w     = (const float*)d_in[1];
    const float* proj  = (const float*)d_in[2];
    const float* u1    = (const float*)d_in[3];
    const float* u2    = (const float*)d_in[4];
    const float* u3    = (const float*)d_in[5];
    const int*   cnts  = (const int*)d_in[6];
    float* out = (float*)d_out;

    int N = in_sizes[0] / (CCH * DD);

    cudaFuncSetAttribute(main_kernel, cudaFuncAttributeMaxDynamicSharedMemorySize, SMEM_BYTES);

    prep_kernel<<<NS * CCH, 256>>>(w, proj, u1, u2, u3);

    dim3 grid((N + NPB - 1) / NPB + NS, CCH / CPB);
    main_kernel<<<grid, THREADS, SMEM_BYTES>>>(x, cnts, out, N);
}